// round 1
// baseline (speedup 1.0000x reference)
#include <cuda_runtime.h>
#include <cuda_bf16.h>
#include <math_constants.h>

#define N_NODES 8192
#define DEG     16
#define NBR     (DEG + 1)
#define F_IN    1024
#define F_OUT   128
#define H_HEADS 8
#define J_DIM   (H_HEADS * F_OUT)   // 1024

// Scratch (allocation-free rule: __device__ globals)
__device__ float g_h[N_NODES * J_DIM];        // h_all[n][h*128+o], 32 MB
__device__ float g_sdst[H_HEADS * N_NODES];   // [h][n]
__device__ float g_ssrc[H_HEADS * N_NODES];   // [h][n]

// ---------------------------------------------------------------------------
// Kernel 1: projection GEMM  C[n, h*128+o] = features[n,:] @ W[h,:,o] + bW[h,o]
// Tiles: BM=128, BN=128 (== one head), BK=8; 256 threads, 8x8 per thread.
// ---------------------------------------------------------------------------
#define BM 128
#define BN 128
#define BK 8

__global__ __launch_bounds__(256, 2)
void gemm_kernel(const float* __restrict__ A,    // [N, F_IN]
                 const float* __restrict__ W,    // [H, F_IN, F_OUT]
                 const float* __restrict__ bW)   // [H, F_OUT]
{
    __shared__ float As[BK][BM];
    __shared__ float Bs[BK][BN];

    const int bx = blockIdx.x;          // head index (BN == F_OUT)
    const int by = blockIdx.y;          // row tile
    const int tid = threadIdx.x;
    const int tx = tid & 15;            // 0..15
    const int ty = tid >> 4;            // 0..15

    const int m0 = by * BM;
    const float* Bp = W + (size_t)bx * F_IN * F_OUT;

    // load mapping
    const int arow = tid >> 1;           // 0..127
    const int acol = (tid & 1) * 4;      // 0 or 4
    const int brow = tid >> 5;           // 0..7
    const int bcol = (tid & 31) * 4;     // 0..124

    float acc[8][8];
    #pragma unroll
    for (int i = 0; i < 8; i++)
        #pragma unroll
        for (int j = 0; j < 8; j++) acc[i][j] = 0.f;

    for (int k0 = 0; k0 < F_IN; k0 += BK) {
        float4 av = *(const float4*)(A + (size_t)(m0 + arow) * F_IN + k0 + acol);
        As[acol + 0][arow] = av.x;
        As[acol + 1][arow] = av.y;
        As[acol + 2][arow] = av.z;
        As[acol + 3][arow] = av.w;

        float4 bv = *(const float4*)(Bp + (size_t)(k0 + brow) * F_OUT + bcol);
        *(float4*)&Bs[brow][bcol] = bv;

        __syncthreads();

        #pragma unroll
        for (int k = 0; k < BK; k++) {
            float ar[8], br[8];
            *(float4*)&ar[0] = *(const float4*)&As[k][ty * 8];
            *(float4*)&ar[4] = *(const float4*)&As[k][ty * 8 + 4];
            *(float4*)&br[0] = *(const float4*)&Bs[k][tx * 8];
            *(float4*)&br[4] = *(const float4*)&Bs[k][tx * 8 + 4];
            #pragma unroll
            for (int i = 0; i < 8; i++)
                #pragma unroll
                for (int j = 0; j < 8; j++)
                    acc[i][j] = fmaf(ar[i], br[j], acc[i][j]);
        }
        __syncthreads();
    }

    // epilogue: bias + store to g_h[n][bx*128 + col]
    const float* bias = bW + bx * F_OUT;
    #pragma unroll
    for (int i = 0; i < 8; i++) {
        int row = m0 + ty * 8 + i;
        float* crow = g_h + (size_t)row * J_DIM + bx * F_OUT + tx * 8;
        #pragma unroll
        for (int j = 0; j < 8; j += 4) {
            float4 v;
            v.x = acc[i][j + 0] + bias[tx * 8 + j + 0];
            v.y = acc[i][j + 1] + bias[tx * 8 + j + 1];
            v.z = acc[i][j + 2] + bias[tx * 8 + j + 2];
            v.w = acc[i][j + 3] + bias[tx * 8 + j + 3];
            *(float4*)(crow + j) = v;
        }
    }
}

// ---------------------------------------------------------------------------
// Kernel 2: per-(h,n) score dot-products  s_dst[h,n] = h[h,n,:].a_dst[h,:]
// One warp per (h,n); lane handles 4 contiguous floats.
// ---------------------------------------------------------------------------
__global__ void s_kernel(const float* __restrict__ a)   // [H, 2*F_OUT]
{
    int w = (blockIdx.x * blockDim.x + threadIdx.x) >> 5;
    int lane = threadIdx.x & 31;
    if (w >= H_HEADS * N_NODES) return;
    int h = w & (H_HEADS - 1);
    int n = w >> 3;

    const float* hv = g_h + (size_t)n * J_DIM + h * F_OUT + lane * 4;
    const float* ad = a + h * (2 * F_OUT) + lane * 4;
    const float* as = ad + F_OUT;

    float4 hvv = *(const float4*)hv;
    float4 adv = *(const float4*)ad;
    float4 asv = *(const float4*)as;

    float pd = hvv.x * adv.x + hvv.y * adv.y + hvv.z * adv.z + hvv.w * adv.w;
    float ps = hvv.x * asv.x + hvv.y * asv.y + hvv.z * asv.z + hvv.w * asv.w;

    #pragma unroll
    for (int off = 16; off > 0; off >>= 1) {
        pd += __shfl_xor_sync(0xFFFFFFFFu, pd, off);
        ps += __shfl_xor_sync(0xFFFFFFFFu, ps, off);
    }
    if (lane == 0) {
        g_sdst[h * N_NODES + n] = pd;
        g_ssrc[h * N_NODES + n] = ps;
    }
}

// ---------------------------------------------------------------------------
// Kernel 3: softmax over 17 neighbors + weighted gather-aggregate.
// One warp per (h,n). Lanes 0..16 own one neighbor's score; all 32 lanes
// aggregate 4 floats each of the 128-wide feature slice.
// ---------------------------------------------------------------------------
__global__ void attn_kernel(const int* __restrict__ adj,
                            const float* __restrict__ ba,
                            float* __restrict__ out)
{
    int w = (blockIdx.x * blockDim.x + threadIdx.x) >> 5;
    int lane = threadIdx.x & 31;
    if (w >= H_HEADS * N_NODES) return;
    int h = w & (H_HEADS - 1);
    int n = w >> 3;

    int nbr = 0;
    float sc = -CUDART_INF_F;
    if (lane < NBR) {
        nbr = (lane < DEG) ? adj[n * DEG + lane] : n;
        float x = g_sdst[h * N_NODES + n] + g_ssrc[h * N_NODES + nbr] + ba[h];
        sc = (x > 0.f) ? x : 0.2f * x;
    }

    // max over 17 scores
    float m = sc;
    #pragma unroll
    for (int off = 16; off > 0; off >>= 1)
        m = fmaxf(m, __shfl_xor_sync(0xFFFFFFFFu, m, off));

    float e = (lane < NBR) ? __expf(sc - m) : 0.f;
    float s = e;
    #pragma unroll
    for (int off = 16; off > 0; off >>= 1)
        s += __shfl_xor_sync(0xFFFFFFFFu, s, off);

    float alpha = e / s;    // valid for lanes < NBR

    float4 acc = make_float4(0.f, 0.f, 0.f, 0.f);
    const float* base = g_h + (size_t)h * 0 + h * F_OUT + lane * 4; // column offset
    #pragma unroll
    for (int d = 0; d < NBR; d++) {
        int nb = __shfl_sync(0xFFFFFFFFu, nbr, d);
        float al = __shfl_sync(0xFFFFFFFFu, alpha, d);
        float4 v = *(const float4*)(g_h + (size_t)nb * J_DIM + h * F_OUT + lane * 4);
        acc.x = fmaf(al, v.x, acc.x);
        acc.y = fmaf(al, v.y, acc.y);
        acc.z = fmaf(al, v.z, acc.z);
        acc.w = fmaf(al, v.w, acc.w);
    }
    (void)base;
    *(float4*)(out + (size_t)n * J_DIM + h * F_OUT + lane * 4) = acc;
}

// ---------------------------------------------------------------------------
extern "C" void kernel_launch(void* const* d_in, const int* in_sizes, int n_in,
                              void* d_out, int out_size)
{
    const float* features = (const float*)d_in[0];   // [8192, 1024]
    const int*   adj      = (const int*)  d_in[1];   // [8192, 16]
    const float* W        = (const float*)d_in[2];   // [8, 1024, 128]
    const float* bW       = (const float*)d_in[3];   // [8, 128]
    const float* a        = (const float*)d_in[4];   // [8, 256]
    const float* ba       = (const float*)d_in[5];   // [8]
    float* out = (float*)d_out;                      // [8192, 1024]

    // 1) projection GEMM
    dim3 ggrid(J_DIM / BN, N_NODES / BM);   // (8, 64)
    gemm_kernel<<<ggrid, 256>>>(features, W, bW);

    // 2) attention score dots: 65536 warps
    int warps = H_HEADS * N_NODES;
    int blocks = (warps * 32) / 256;
    s_kernel<<<blocks, 256>>>(a);

    // 3) softmax + aggregate
    attn_kernel<<<blocks, 256>>>(adj, ba, out);
}

// round 4
// speedup vs baseline: 1.2704x; 1.2704x over previous
#include <cuda_runtime.h>
#include <cuda_bf16.h>
#include <math_constants.h>
#include <cstdint>

#define N_NODES 8192
#define DEG     16
#define NBR     (DEG + 1)
#define F_IN    1024
#define F_OUT   128
#define H_HEADS 8
#define J_DIM   (H_HEADS * F_OUT)   // 1024
#define BK      32
#define NCHUNK  (F_IN / BK)         // 32

#define AS_STRIDE 36                 // floats per row (pad: conflict-free frags, 16B-aligned rows)
#define TILE_BYTES (128 * AS_STRIDE * 4)   // 18432
#define HS_STRIDE 132                // epilogue staging row stride (floats)

// Scratch (allocation-free rule: __device__ globals)
__device__ float g_h[N_NODES * J_DIM];            // 32 MB projected features
__device__ float g_Wt[H_HEADS * F_OUT * F_IN];    // 4 MB  W as [h][o][k] (K-major)
__device__ float g_sdst[H_HEADS * N_NODES];
__device__ float g_ssrc[H_HEADS * N_NODES];

// ---------------------------------------------------------------------------
static __device__ __forceinline__ uint32_t smem_u32(const void* p) {
    uint32_t a;
    asm("{ .reg .u64 t; cvta.to.shared.u64 t, %1; cvt.u32.u64 %0, t; }" : "=r"(a) : "l"(p));
    return a;
}
#define CP_ASYNC16(dst_u32, src_ptr) \
    asm volatile("cp.async.cg.shared.global [%0], [%1], 16;" :: "r"(dst_u32), "l"(src_ptr))
#define CP_COMMIT() asm volatile("cp.async.commit_group;" ::: "memory")
#define CP_WAIT(n)  asm volatile("cp.async.wait_group %0;" :: "n"(n) : "memory")

static __device__ __forceinline__ uint32_t f2tf(float x) {   // round-to-nearest tf32
    uint32_t y;
    asm("cvt.rna.tf32.f32 %0, %1;" : "=r"(y) : "f"(x));
    return y;
}
static __device__ __forceinline__ void split_tf32(float v, uint32_t& hi, uint32_t& lo) {
    hi = f2tf(v);
    lo = f2tf(v - __uint_as_float(hi));
}
static __device__ __forceinline__ void mma_tf32(float* c, const uint32_t* a, const uint32_t* b) {
    asm volatile(
        "mma.sync.aligned.m16n8k8.row.col.f32.tf32.tf32.f32 "
        "{%0,%1,%2,%3}, {%4,%5,%6,%7}, {%8,%9}, {%0,%1,%2,%3};"
        : "+f"(c[0]), "+f"(c[1]), "+f"(c[2]), "+f"(c[3])
        : "r"(a[0]), "r"(a[1]), "r"(a[2]), "r"(a[3]), "r"(b[0]), "r"(b[1]));
}

// ---------------------------------------------------------------------------
// Kernel 0: W[h][k][o] -> Wt[h][o][k]  (K-major for the MMA B operand)
// ---------------------------------------------------------------------------
__global__ void transposeW(const float* __restrict__ W) {
    __shared__ float t[32][33];
    int h = blockIdx.z, o0 = blockIdx.x * 32, k0 = blockIdx.y * 32;
    const float* Wp = W + (size_t)h * F_IN * F_OUT;
    float* Tp = g_Wt + (size_t)h * F_OUT * F_IN;
    int tx = threadIdx.x, ty = threadIdx.y;
    #pragma unroll
    for (int r = 0; r < 32; r += 8)
        t[ty + r][tx] = Wp[(size_t)(k0 + ty + r) * F_OUT + o0 + tx];
    __syncthreads();
    #pragma unroll
    for (int r = 0; r < 32; r += 8)
        Tp[(size_t)(o0 + ty + r) * F_IN + k0 + tx] = t[tx][ty + r];
}

// ---------------------------------------------------------------------------
// Kernel 1: 3xTF32 mma.sync GEMM, tile 128x128(one head) x K=1024, cp.async
// double-buffered. Epilogue: bias, coalesced g_h store, fused score dots.
// ---------------------------------------------------------------------------
__global__ __launch_bounds__(256)
void gemm_tc(const float* __restrict__ A,      // [N, F_IN]
             const float* __restrict__ bW,     // [H, F_OUT]
             const float* __restrict__ a_att)  // [H, 2*F_OUT]
{
    extern __shared__ float4 dsm4[];
    float* smem = (float*)dsm4;
    float* As[2] = { smem,                       smem + 128 * AS_STRIDE };
    float* Bs[2] = { smem + 2 * 128 * AS_STRIDE, smem + 3 * 128 * AS_STRIDE };

    const int head = blockIdx.x;
    const int m0   = blockIdx.y * 128;
    const int tid  = threadIdx.x;
    const int wid  = tid >> 5;
    const int lane = tid & 31;
    const int warp_m = wid >> 2;          // 0..1
    const int warp_n = wid & 3;           // 0..3
    const int gid = lane >> 2;            // 0..7
    const int tig = lane & 3;             // 0..3

    const float* Ap = A    + (size_t)m0   * F_IN;
    const float* Bp = g_Wt + (size_t)head * F_OUT * F_IN;

    int ldr[4], ldc[4];
    #pragma unroll
    for (int j = 0; j < 4; j++) {
        int idx = tid + j * 256;
        ldr[j] = idx >> 3;
        ldc[j] = (idx & 7) * 4;
    }

    auto issue_chunk = [&](int chunk) {
        int k0 = chunk * BK;
        int buf = chunk & 1;
        uint32_t as_u = smem_u32(As[buf]);
        uint32_t bs_u = smem_u32(Bs[buf]);
        #pragma unroll
        for (int j = 0; j < 4; j++)
            CP_ASYNC16(as_u + (ldr[j] * AS_STRIDE + ldc[j]) * 4,
                       Ap + (size_t)ldr[j] * F_IN + k0 + ldc[j]);
        #pragma unroll
        for (int j = 0; j < 4; j++)
            CP_ASYNC16(bs_u + (ldr[j] * AS_STRIDE + ldc[j]) * 4,
                       Bp + (size_t)ldr[j] * F_IN + k0 + ldc[j]);
        CP_COMMIT();
    };

    float acc[4][4][4];
    #pragma unroll
    for (int i = 0; i < 4; i++)
        #pragma unroll
        for (int j = 0; j < 4; j++)
            #pragma unroll
            for (int r = 0; r < 4; r++) acc[i][j][r] = 0.f;

    issue_chunk(0);
    issue_chunk(1);

    for (int i = 0; i < NCHUNK; i++) {
        if (i < NCHUNK - 1) { CP_WAIT(1); } else { CP_WAIT(0); }
        __syncthreads();
        const float* a_s = As[i & 1];
        const float* b_s = Bs[i & 1];

        #pragma unroll
        for (int ks = 0; ks < 4; ks++) {
            const int kk = ks * 8;

            // B fragments (hi/lo split)
            uint32_t bf_hi[4][2], bf_lo[4][2];
            #pragma unroll
            for (int nt = 0; nt < 4; nt++) {
                int n = warp_n * 32 + nt * 8 + gid;
                split_tf32(b_s[n * AS_STRIDE + kk + tig    ], bf_hi[nt][0], bf_lo[nt][0]);
                split_tf32(b_s[n * AS_STRIDE + kk + tig + 4], bf_hi[nt][1], bf_lo[nt][1]);
            }

            #pragma unroll
            for (int mt = 0; mt < 4; mt++) {
                int row = warp_m * 64 + mt * 16 + gid;
                uint32_t a_hi[4], a_lo[4];
                split_tf32(a_s[(row    ) * AS_STRIDE + kk + tig    ], a_hi[0], a_lo[0]);
                split_tf32(a_s[(row + 8) * AS_STRIDE + kk + tig    ], a_hi[1], a_lo[1]);
                split_tf32(a_s[(row    ) * AS_STRIDE + kk + tig + 4], a_hi[2], a_lo[2]);
                split_tf32(a_s[(row + 8) * AS_STRIDE + kk + tig + 4], a_hi[3], a_lo[3]);
                #pragma unroll
                for (int nt = 0; nt < 4; nt++) {
                    mma_tf32(acc[mt][nt], a_hi, bf_hi[nt]);   // hi*hi
                    mma_tf32(acc[mt][nt], a_lo, bf_hi[nt]);   // lo*hi
                    mma_tf32(acc[mt][nt], a_hi, bf_lo[nt]);   // hi*lo
                }
            }
        }
        __syncthreads();
        if (i + 2 < NCHUNK) issue_chunk(i + 2);
    }

    // ---- epilogue: stage (acc+bias) into smem, then dots + coalesced stores ----
    float* hs = smem;   // 128 x HS_STRIDE floats = 67584 B <= 73728 B
    const float* bias = bW + head * F_OUT;
    #pragma unroll
    for (int mt = 0; mt < 4; mt++) {
        #pragma unroll
        for (int nt = 0; nt < 4; nt++) {
            int row = warp_m * 64 + mt * 16 + gid;
            int col = warp_n * 32 + nt * 8 + 2 * tig;
            float b0 = bias[col], b1 = bias[col + 1];
            float2 v0 = make_float2(acc[mt][nt][0] + b0, acc[mt][nt][1] + b1);
            float2 v1 = make_float2(acc[mt][nt][2] + b0, acc[mt][nt][3] + b1);
            *(float2*)&hs[(size_t)row * HS_STRIDE + col]       = v0;
            *(float2*)&hs[(size_t)(row + 8) * HS_STRIDE + col] = v1;
        }
    }
    __syncthreads();

    // score dots: warp w owns rows w*16 .. w*16+15
    const float* ad = a_att + head * 2 * F_OUT;
    const float* as = ad + F_OUT;
    #pragma unroll
    for (int it = 0; it < 16; it++) {
        int row = wid * 16 + it;
        float pd = 0.f, ps = 0.f;
        #pragma unroll
        for (int j = 0; j < 4; j++) {
            int c = lane + 32 * j;
            float v = hs[(size_t)row * HS_STRIDE + c];
            pd = fmaf(v, ad[c], pd);
            ps = fmaf(v, as[c], ps);
        }
        #pragma unroll
        for (int off = 16; off > 0; off >>= 1) {
            pd += __shfl_xor_sync(0xFFFFFFFFu, pd, off);
            ps += __shfl_xor_sync(0xFFFFFFFFu, ps, off);
        }
        if (lane == 0) {
            g_sdst[head * N_NODES + m0 + row] = pd;
            g_ssrc[head * N_NODES + m0 + row] = ps;
        }
    }

    // coalesced g_h stores: 4096 float4
    #pragma unroll
    for (int it = 0; it < 16; it++) {
        int idx = tid + it * 256;
        int row = idx >> 5;
        int c4  = (idx & 31) * 4;
        float4 v = *(const float4*)&hs[(size_t)row * HS_STRIDE + c4];
        *(float4*)(g_h + (size_t)(m0 + row) * J_DIM + head * F_OUT + c4) = v;
    }
}

// ---------------------------------------------------------------------------
// Kernel 2: softmax over 17 neighbors + weighted gather-aggregate.
// One warp per (h,n).
// ---------------------------------------------------------------------------
__global__ void attn_kernel(const int* __restrict__ adj,
                            const float* __restrict__ ba,
                            float* __restrict__ out)
{
    int w = (blockIdx.x * blockDim.x + threadIdx.x) >> 5;
    int lane = threadIdx.x & 31;
    if (w >= H_HEADS * N_NODES) return;
    int h = w & (H_HEADS - 1);
    int n = w >> 3;

    int nbr = 0;
    float sc = -CUDART_INF_F;
    if (lane < NBR) {
        nbr = (lane < DEG) ? adj[n * DEG + lane] : n;
        float x = g_sdst[h * N_NODES + n] + g_ssrc[h * N_NODES + nbr] + ba[h];
        sc = (x > 0.f) ? x : 0.2f * x;
    }

    float m = sc;
    #pragma unroll
    for (int off = 16; off > 0; off >>= 1)
        m = fmaxf(m, __shfl_xor_sync(0xFFFFFFFFu, m, off));

    float e = (lane < NBR) ? __expf(sc - m) : 0.f;
    float s = e;
    #pragma unroll
    for (int off = 16; off > 0; off >>= 1)
        s += __shfl_xor_sync(0xFFFFFFFFu, s, off);

    float alpha = e / s;

    float4 acc = make_float4(0.f, 0.f, 0.f, 0.f);
    #pragma unroll
    for (int d = 0; d < NBR; d++) {
        int nb = __shfl_sync(0xFFFFFFFFu, nbr, d);
        float al = __shfl_sync(0xFFFFFFFFu, alpha, d);
        float4 v = *(const float4*)(g_h + (size_t)nb * J_DIM + h * F_OUT + lane * 4);
        acc.x = fmaf(al, v.x, acc.x);
        acc.y = fmaf(al, v.y, acc.y);
        acc.z = fmaf(al, v.z, acc.z);
        acc.w = fmaf(al, v.w, acc.w);
    }
    *(float4*)(out + (size_t)n * J_DIM + h * F_OUT + lane * 4) = acc;
}

// ---------------------------------------------------------------------------
extern "C" void kernel_launch(void* const* d_in, const int* in_sizes, int n_in,
                              void* d_out, int out_size)
{
    const float* features = (const float*)d_in[0];   // [8192, 1024]
    const int*   adj      = (const int*)  d_in[1];   // [8192, 16]
    const float* W        = (const float*)d_in[2];   // [8, 1024, 128]
    const float* bW       = (const float*)d_in[3];   // [8, 128]
    const float* a        = (const float*)d_in[4];   // [8, 256]
    const float* ba       = (const float*)d_in[5];   // [8]
    float* out = (float*)d_out;                      // [8192, 1024]

    // 0) transpose W to K-major
    transposeW<<<dim3(F_OUT / 32, F_IN / 32, H_HEADS), dim3(32, 8)>>>(W);

    // 1) 3xTF32 mma.sync projection GEMM (+ fused bias & score dots)
    const int dsmem = 4 * TILE_BYTES;    // 73728 B
    cudaFuncSetAttribute(gemm_tc, cudaFuncAttributeMaxDynamicSharedMemorySize, dsmem);
    gemm_tc<<<dim3(H_HEADS, N_NODES / 128), 256, dsmem>>>(features, bW, a);

    // 2) softmax + aggregate
    int warps = H_HEADS * N_NODES;
    attn_kernel<<<(warps * 32) / 256, 256>>>(adj, ba, out);
}

// round 5
// speedup vs baseline: 1.8247x; 1.4364x over previous
#include <cuda_runtime.h>
#include <cuda_bf16.h>
#include <math_constants.h>
#include <cstdint>

#define N_NODES 8192
#define DEG     16
#define NBR     (DEG + 1)
#define F_IN    1024
#define F_OUT   128
#define H_HEADS 8
#define J_DIM   (H_HEADS * F_OUT)   // 1024
#define BK      32
#define NCHUNK  (F_IN / BK)         // 32

#define ROW_BF   40                  // bf16 per smem row (80 B, 16B-aligned, conflict-free)
#define ARR_BF   (128 * ROW_BF)      // bf16 per tile array (5120)
#define HS_STRIDE 132                // epilogue staging row stride (floats)

// Scratch (allocation-free rule: __device__ globals)
__device__ float g_h[N_NODES * J_DIM];                 // 32 MB projected features
__device__ __nv_bfloat16 g_Ahi[N_NODES * F_IN];        // 16 MB
__device__ __nv_bfloat16 g_Alo[N_NODES * F_IN];        // 16 MB
__device__ __nv_bfloat16 g_Whi[H_HEADS * F_OUT * F_IN]; // 2 MB  [h][o][k]
__device__ __nv_bfloat16 g_Wlo[H_HEADS * F_OUT * F_IN]; // 2 MB
__device__ float g_sdst[H_HEADS * N_NODES];
__device__ float g_ssrc[H_HEADS * N_NODES];

// ---------------------------------------------------------------------------
static __device__ __forceinline__ uint32_t smem_u32(const void* p) {
    uint32_t a;
    asm("{ .reg .u64 t; cvta.to.shared.u64 t, %1; cvt.u32.u64 %0, t; }" : "=r"(a) : "l"(p));
    return a;
}
#define CP_ASYNC16(dst_u32, src_ptr) \
    asm volatile("cp.async.cg.shared.global [%0], [%1], 16;" :: "r"(dst_u32), "l"(src_ptr))
#define CP_COMMIT() asm volatile("cp.async.commit_group;" ::: "memory")
#define CP_WAIT(n)  asm volatile("cp.async.wait_group %0;" :: "n"(n) : "memory")

static __device__ __forceinline__ void mma_bf16(float* c, const uint32_t* a, const uint32_t* b) {
    asm volatile(
        "mma.sync.aligned.m16n8k16.row.col.f32.bf16.bf16.f32 "
        "{%0,%1,%2,%3}, {%4,%5,%6,%7}, {%8,%9}, {%0,%1,%2,%3};"
        : "+f"(c[0]), "+f"(c[1]), "+f"(c[2]), "+f"(c[3])
        : "r"(a[0]), "r"(a[1]), "r"(a[2]), "r"(a[3]), "r"(b[0]), "r"(b[1]));
}
static __device__ __forceinline__ void split_bf16(float v, __nv_bfloat16& hi, __nv_bfloat16& lo) {
    hi = __float2bfloat16(v);
    lo = __float2bfloat16(v - __bfloat162float(hi));
}

// ---------------------------------------------------------------------------
// Kernel 0a: split features into bf16 hi/lo (same [n][k] layout)
// ---------------------------------------------------------------------------
__global__ void splitA(const float* __restrict__ A) {
    int idx = (blockIdx.x * blockDim.x + threadIdx.x) * 4;   // 4 floats per thread
    float4 v = *(const float4*)(A + idx);
    __nv_bfloat16 h0, h1, h2, h3, l0, l1, l2, l3;
    split_bf16(v.x, h0, l0); split_bf16(v.y, h1, l1);
    split_bf16(v.z, h2, l2); split_bf16(v.w, h3, l3);
    __nv_bfloat162* ph = (__nv_bfloat162*)(g_Ahi + idx);
    __nv_bfloat162* pl = (__nv_bfloat162*)(g_Alo + idx);
    ph[0] = __nv_bfloat162(h0, h1); ph[1] = __nv_bfloat162(h2, h3);
    pl[0] = __nv_bfloat162(l0, l1); pl[1] = __nv_bfloat162(l2, l3);
}

// ---------------------------------------------------------------------------
// Kernel 0b: W[h][k][o] -> Whi/Wlo[h][o][k]  (transpose + split)
// ---------------------------------------------------------------------------
__global__ void splitW(const float* __restrict__ W) {
    __shared__ float t[32][33];
    int h = blockIdx.z, o0 = blockIdx.x * 32, k0 = blockIdx.y * 32;
    const float* Wp = W + (size_t)h * F_IN * F_OUT;
    size_t tbase = (size_t)h * F_OUT * F_IN;
    int tx = threadIdx.x, ty = threadIdx.y;
    #pragma unroll
    for (int r = 0; r < 32; r += 8)
        t[ty + r][tx] = Wp[(size_t)(k0 + ty + r) * F_OUT + o0 + tx];
    __syncthreads();
    #pragma unroll
    for (int r = 0; r < 32; r += 8) {
        float v = t[tx][ty + r];
        __nv_bfloat16 hi, lo;
        split_bf16(v, hi, lo);
        size_t off = tbase + (size_t)(o0 + ty + r) * F_IN + k0 + tx;
        g_Whi[off] = hi;
        g_Wlo[off] = lo;
    }
}

// ---------------------------------------------------------------------------
// Kernel 1: bf16x3 mma.sync GEMM, tile 128x128(one head) x K=1024, cp.async
// double-buffered. Epilogue: bias, fused score dots, coalesced g_h store.
// ---------------------------------------------------------------------------
__global__ __launch_bounds__(256)
void gemm_tc(const float* __restrict__ bW,     // [H, F_OUT]
             const float* __restrict__ a_att)  // [H, 2*F_OUT]
{
    extern __shared__ float4 dsm4[];
    __nv_bfloat16* sb = (__nv_bfloat16*)dsm4;
    // layout: [buf][4 arrays: Ahi, Alo, Bhi, Blo] each ARR_BF bf16
    __nv_bfloat16* Sa_hi[2] = { sb,              sb + 4 * ARR_BF };
    __nv_bfloat16* Sa_lo[2] = { sb + 1 * ARR_BF, sb + 5 * ARR_BF };
    __nv_bfloat16* Sb_hi[2] = { sb + 2 * ARR_BF, sb + 6 * ARR_BF };
    __nv_bfloat16* Sb_lo[2] = { sb + 3 * ARR_BF, sb + 7 * ARR_BF };

    const int head = blockIdx.x;
    const int m0   = blockIdx.y * 128;
    const int tid  = threadIdx.x;
    const int wid  = tid >> 5;
    const int lane = tid & 31;
    const int warp_m = wid >> 2;          // 0..1
    const int warp_n = wid & 3;           // 0..3
    const int gid = lane >> 2;            // 0..7
    const int tig = lane & 3;             // 0..3

    const __nv_bfloat16* Ah = g_Ahi + (size_t)m0 * F_IN;
    const __nv_bfloat16* Al = g_Alo + (size_t)m0 * F_IN;
    const __nv_bfloat16* Bh = g_Whi + (size_t)head * F_OUT * F_IN;
    const __nv_bfloat16* Bl = g_Wlo + (size_t)head * F_OUT * F_IN;

    // loader: each tile array = 128 rows x 32 bf16 = 512 x 16B; 2 slots/thread
    int ldr[2], lds_[2];
    #pragma unroll
    for (int j = 0; j < 2; j++) {
        int idx = tid + j * 256;
        ldr[j]  = idx >> 2;        // row 0..127
        lds_[j] = (idx & 3) * 8;   // bf16 col offset 0,8,16,24
    }

    auto issue_chunk = [&](int chunk) {
        int k0 = chunk * BK;
        int buf = chunk & 1;
        uint32_t ah_u = smem_u32(Sa_hi[buf]);
        uint32_t al_u = smem_u32(Sa_lo[buf]);
        uint32_t bh_u = smem_u32(Sb_hi[buf]);
        uint32_t bl_u = smem_u32(Sb_lo[buf]);
        #pragma unroll
        for (int j = 0; j < 2; j++) {
            uint32_t doff = (uint32_t)(ldr[j] * ROW_BF + lds_[j]) * 2;
            size_t   soff = (size_t)ldr[j] * F_IN + k0 + lds_[j];
            CP_ASYNC16(ah_u + doff, Ah + soff);
            CP_ASYNC16(al_u + doff, Al + soff);
            CP_ASYNC16(bh_u + doff, Bh + soff);
            CP_ASYNC16(bl_u + doff, Bl + soff);
        }
        CP_COMMIT();
    };

    float acc[4][4][4];
    #pragma unroll
    for (int i = 0; i < 4; i++)
        #pragma unroll
        for (int j = 0; j < 4; j++)
            #pragma unroll
            for (int r = 0; r < 4; r++) acc[i][j][r] = 0.f;

    issue_chunk(0);
    issue_chunk(1);

    for (int i = 0; i < NCHUNK; i++) {
        if (i < NCHUNK - 1) { CP_WAIT(1); } else { CP_WAIT(0); }
        __syncthreads();
        const int buf = i & 1;
        const uint32_t* ah = (const uint32_t*)Sa_hi[buf];
        const uint32_t* al = (const uint32_t*)Sa_lo[buf];
        const uint32_t* bh = (const uint32_t*)Sb_hi[buf];
        const uint32_t* bl = (const uint32_t*)Sb_lo[buf];

        #pragma unroll
        for (int ks = 0; ks < 2; ks++) {          // K=16 per mma
            const int kw = ks * 8;                // word offset (bf16 pairs)

            uint32_t bfh[4][2], bfl[4][2];
            #pragma unroll
            for (int nt = 0; nt < 4; nt++) {
                int n = warp_n * 32 + nt * 8 + gid;
                int w0 = n * (ROW_BF / 2) + kw + tig;
                bfh[nt][0] = bh[w0];     bfh[nt][1] = bh[w0 + 4];
                bfl[nt][0] = bl[w0];     bfl[nt][1] = bl[w0 + 4];
            }

            #pragma unroll
            for (int mt = 0; mt < 4; mt++) {
                int row = warp_m * 64 + mt * 16 + gid;
                int w0 = row * (ROW_BF / 2) + kw + tig;
                int w1 = (row + 8) * (ROW_BF / 2) + kw + tig;
                uint32_t afh[4], afl[4];
                afh[0] = ah[w0]; afh[1] = ah[w1]; afh[2] = ah[w0 + 4]; afh[3] = ah[w1 + 4];
                afl[0] = al[w0]; afl[1] = al[w1]; afl[2] = al[w0 + 4]; afl[3] = al[w1 + 4];
                #pragma unroll
                for (int nt = 0; nt < 4; nt++)
                    mma_bf16(acc[mt][nt], afh, bfh[nt]);   // hi*hi
                #pragma unroll
                for (int nt = 0; nt < 4; nt++)
                    mma_bf16(acc[mt][nt], afl, bfh[nt]);   // lo*hi
                #pragma unroll
                for (int nt = 0; nt < 4; nt++)
                    mma_bf16(acc[mt][nt], afh, bfl[nt]);   // hi*lo
            }
        }
        __syncthreads();
        if (i + 2 < NCHUNK) issue_chunk(i + 2);
    }

    // ---- epilogue: stage (acc+bias) into smem, then dots + coalesced stores ----
    float* hs = (float*)dsm4;   // 128 x HS_STRIDE floats = 67584 B <= dsmem
    const float* bias = bW + head * F_OUT;
    #pragma unroll
    for (int mt = 0; mt < 4; mt++) {
        #pragma unroll
        for (int nt = 0; nt < 4; nt++) {
            int row = warp_m * 64 + mt * 16 + gid;
            int col = warp_n * 32 + nt * 8 + 2 * tig;
            float b0 = bias[col], b1 = bias[col + 1];
            float2 v0 = make_float2(acc[mt][nt][0] + b0, acc[mt][nt][1] + b1);
            float2 v1 = make_float2(acc[mt][nt][2] + b0, acc[mt][nt][3] + b1);
            *(float2*)&hs[(size_t)row * HS_STRIDE + col]       = v0;
            *(float2*)&hs[(size_t)(row + 8) * HS_STRIDE + col] = v1;
        }
    }
    __syncthreads();

    // score dots: warp w owns rows w*16 .. w*16+15
    const float* ad = a_att + head * 2 * F_OUT;
    const float* as = ad + F_OUT;
    #pragma unroll
    for (int it = 0; it < 16; it++) {
        int row = wid * 16 + it;
        float pd = 0.f, ps = 0.f;
        #pragma unroll
        for (int j = 0; j < 4; j++) {
            int c = lane + 32 * j;
            float v = hs[(size_t)row * HS_STRIDE + c];
            pd = fmaf(v, ad[c], pd);
            ps = fmaf(v, as[c], ps);
        }
        #pragma unroll
        for (int off = 16; off > 0; off >>= 1) {
            pd += __shfl_xor_sync(0xFFFFFFFFu, pd, off);
            ps += __shfl_xor_sync(0xFFFFFFFFu, ps, off);
        }
        if (lane == 0) {
            g_sdst[head * N_NODES + m0 + row] = pd;
            g_ssrc[head * N_NODES + m0 + row] = ps;
        }
    }

    // coalesced g_h stores: 4096 float4
    #pragma unroll
    for (int it = 0; it < 16; it++) {
        int idx = tid + it * 256;
        int row = idx >> 5;
        int c4  = (idx & 31) * 4;
        float4 v = *(const float4*)&hs[(size_t)row * HS_STRIDE + c4];
        *(float4*)(g_h + (size_t)(m0 + row) * J_DIM + head * F_OUT + c4) = v;
    }
}

// ---------------------------------------------------------------------------
// Kernel 2: softmax over 17 neighbors + weighted gather-aggregate.
// One warp per (h,n).
// ---------------------------------------------------------------------------
__global__ void attn_kernel(const int* __restrict__ adj,
                            const float* __restrict__ ba,
                            float* __restrict__ out)
{
    int w = (blockIdx.x * blockDim.x + threadIdx.x) >> 5;
    int lane = threadIdx.x & 31;
    if (w >= H_HEADS * N_NODES) return;
    int h = w & (H_HEADS - 1);
    int n = w >> 3;

    int nbr = 0;
    float sc = -CUDART_INF_F;
    if (lane < NBR) {
        nbr = (lane < DEG) ? adj[n * DEG + lane] : n;
        float x = g_sdst[h * N_NODES + n] + g_ssrc[h * N_NODES + nbr] + ba[h];
        sc = (x > 0.f) ? x : 0.2f * x;
    }

    float m = sc;
    #pragma unroll
    for (int off = 16; off > 0; off >>= 1)
        m = fmaxf(m, __shfl_xor_sync(0xFFFFFFFFu, m, off));

    float e = (lane < NBR) ? __expf(sc - m) : 0.f;
    float s = e;
    #pragma unroll
    for (int off = 16; off > 0; off >>= 1)
        s += __shfl_xor_sync(0xFFFFFFFFu, s, off);

    float alpha = e / s;

    float4 acc = make_float4(0.f, 0.f, 0.f, 0.f);
    #pragma unroll
    for (int d = 0; d < NBR; d++) {
        int nb = __shfl_sync(0xFFFFFFFFu, nbr, d);
        float al = __shfl_sync(0xFFFFFFFFu, alpha, d);
        float4 v = *(const float4*)(g_h + (size_t)nb * J_DIM + h * F_OUT + lane * 4);
        acc.x = fmaf(al, v.x, acc.x);
        acc.y = fmaf(al, v.y, acc.y);
        acc.z = fmaf(al, v.z, acc.z);
        acc.w = fmaf(al, v.w, acc.w);
    }
    *(float4*)(out + (size_t)n * J_DIM + h * F_OUT + lane * 4) = acc;
}

// ---------------------------------------------------------------------------
extern "C" void kernel_launch(void* const* d_in, const int* in_sizes, int n_in,
                              void* d_out, int out_size)
{
    const float* features = (const float*)d_in[0];   // [8192, 1024]
    const int*   adj      = (const int*)  d_in[1];   // [8192, 16]
    const float* W        = (const float*)d_in[2];   // [8, 1024, 128]
    const float* bW       = (const float*)d_in[3];   // [8, 128]
    const float* a        = (const float*)d_in[4];   // [8, 256]
    const float* ba       = (const float*)d_in[5];   // [8]
    float* out = (float*)d_out;                      // [8192, 1024]

    // 0) split features and W into bf16 hi/lo (W also transposed to K-major)
    splitA<<<(N_NODES * F_IN) / (256 * 4), 256>>>(features);
    splitW<<<dim3(F_OUT / 32, F_IN / 32, H_HEADS), dim3(32, 8)>>>(W);

    // 1) bf16x3 mma.sync projection GEMM (+ fused bias & score dots)
    const int dsmem = 8 * ARR_BF * 2;    // 81920 B
    cudaFuncSetAttribute(gemm_tc, cudaFuncAttributeMaxDynamicSharedMemorySize, dsmem);
    gemm_tc<<<dim3(H_HEADS, N_NODES / 128), 256, dsmem>>>(bW, a);

    // 2) softmax + aggregate
    int warps = H_HEADS * N_NODES;
    attn_kernel<<<(warps * 32) / 256, 256>>>(adj, ba, out);
}